// round 14
// baseline (speedup 1.0000x reference)
#include <cuda_runtime.h>
#include <cstdint>

#define MDIM 8192
#define KDIM 8192
#define NDIM 8192

#define ROW_TILES 148
#define COL_TILES 8
#define NBLK (ROW_TILES * COL_TILES)   // 1184 = 148 SMs * 8 blocks/SM

// ---- scratch (device globals; no allocation allowed) ----
__device__ float g_partial[ROW_TILES * KDIM]; // 4.6 MiB
__device__ float g_wcs[KDIM];                 // 32 KiB

// ============================================================
// Kernel 1: partial column sums of W (proven loop, ~41.5us).
// PDL-launched: may begin streaming w while the PREVIOUS graph
// replay's rowdot tail (post-trigger) is still draining.
// Writes only g_partial -> no hazard with old rowdot's g_wcs reads.
// ============================================================
__global__ __launch_bounds__(256, 8) void colsum_partial(const float* __restrict__ w) {
    const int bid  = blockIdx.x;
    const int col4 = (bid & (COL_TILES - 1)) * 256 + threadIdx.x;
    const int rt   = bid >> 3;

    const float4* wp = reinterpret_cast<const float4*>(w) + col4;

    float4 acc = make_float4(0.f, 0.f, 0.f, 0.f);
    #pragma unroll 4
    for (int r = rt; r < NDIM; r += ROW_TILES) {
        float4 v = __ldcs(wp + (size_t)r * (KDIM / 4));
        acc.x += v.x; acc.y += v.y; acc.z += v.z; acc.w += v.w;
    }
    reinterpret_cast<float4*>(g_partial)[(size_t)rt * (KDIM / 4) + col4] = acc;

    cudaTriggerProgrammaticLaunchCompletion();
}

// ============================================================
// Kernel 2: fold 148 partials -> g_wcs (R8-proven scalar
// full-unroll shape). PDL: triggers immediately so rowdot can
// launch + prefetch x; griddepsync guards the partials.
// Writing g_wcs is safe: this grid only starts after ALL
// colsum blocks completed, which (via colsum's PDL gate) is
// after all previous-replay rowdot blocks triggered, i.e.
// after their last g_wcs read.
// ============================================================
__global__ __launch_bounds__(256) void colsum_reduce() {
    cudaTriggerProgrammaticLaunchCompletion();
    cudaGridDependencySynchronize();   // wait: colsum partials visible

    const int k = blockIdx.x * 256 + threadIdx.x;
    const float* p = g_partial + k;

    float s0 = 0.f, s1 = 0.f, s2 = 0.f, s3 = 0.f;
    #pragma unroll
    for (int rt = 0; rt < ROW_TILES; rt += 4) {
        s0 += p[(size_t)(rt + 0) * KDIM];
        s1 += p[(size_t)(rt + 1) * KDIM];
        s2 += p[(size_t)(rt + 2) * KDIM];
        s3 += p[(size_t)(rt + 3) * KDIM];
    }
    g_wcs[k] = (s0 + s1) + (s2 + s3);
}

// ============================================================
// Kernel 3: y[m] = 0.75 * dot(x[m,:], wcs). PDL-overlapped
// x prefetch before griddepsync (hides reduce + gaps).
// Triggers launch-completion right AFTER the last g_wcs read,
// so the next replay's colsum can overlap this kernel's
// reduction/store tail.
// ============================================================
__global__ __launch_bounds__(256) void rowdot(const float* __restrict__ x,
                                              float* __restrict__ y) {
    const int row = blockIdx.x;
    const int tid = threadIdx.x;
    const float4* xp = reinterpret_cast<const float4*>(x) + (size_t)row * (KDIM / 4);

    // prefetch x slice (independent of wcs)
    float4 a[8];
    #pragma unroll
    for (int j = 0; j < 8; ++j)
        a[j] = __ldcs(xp + tid + 256 * j);

    cudaGridDependencySynchronize();   // wait: g_wcs ready

    const float4* wp = reinterpret_cast<const float4*>(g_wcs);
    float s = 0.f;
    #pragma unroll
    for (int j = 0; j < 8; ++j) {
        float4 b = wp[tid + 256 * j];
        s += a[j].x * b.x + a[j].y * b.y + a[j].z * b.z + a[j].w * b.w;
    }

    // last g_wcs read done -> allow next replay's colsum to start
    cudaTriggerProgrammaticLaunchCompletion();

    #pragma unroll
    for (int off = 16; off > 0; off >>= 1)
        s += __shfl_xor_sync(0xFFFFFFFFu, s, off);

    __shared__ float red[8];
    if ((tid & 31) == 0) red[tid >> 5] = s;
    __syncthreads();
    if (tid < 8) {
        float t = red[tid];
        #pragma unroll
        for (int off = 4; off > 0; off >>= 1)
            t += __shfl_xor_sync(0xFFu, t, off);
        if (tid == 0) y[row] = 0.75f * t;
    }
}

extern "C" void kernel_launch(void* const* d_in, const int* in_sizes, int n_in,
                              void* d_out, int out_size) {
    const float* x = (const float*)d_in[0];  // [M, K]
    const float* w = (const float*)d_in[1];  // [N, K]
    float* y = (float*)d_out;                // [M, 1]

    cudaLaunchAttribute pdl;
    pdl.id = cudaLaunchAttributeProgrammaticStreamSerialization;
    pdl.val.programmaticStreamSerializationAllowed = 1;

    {   // k1: PDL so it can overlap the previous replay's rowdot tail
        cudaLaunchConfig_t cfg = {};
        cfg.gridDim = dim3(NBLK);
        cfg.blockDim = dim3(256);
        cfg.attrs = &pdl;
        cfg.numAttrs = 1;
        cudaLaunchKernelEx(&cfg, colsum_partial, w);
    }
    {   // k2: PDL overlap with colsum
        cudaLaunchConfig_t cfg = {};
        cfg.gridDim = dim3(KDIM / 256);
        cfg.blockDim = dim3(256);
        cfg.attrs = &pdl;
        cfg.numAttrs = 1;
        cudaLaunchKernelEx(&cfg, colsum_reduce);
    }
    {   // k3: PDL overlap with reduce
        cudaLaunchConfig_t cfg = {};
        cfg.gridDim = dim3(MDIM);
        cfg.blockDim = dim3(256);
        cfg.attrs = &pdl;
        cfg.numAttrs = 1;
        cudaLaunchKernelEx(&cfg, rowdot, x, y);
    }
}

// round 16
// speedup vs baseline: 1.0072x; 1.0072x over previous
#include <cuda_runtime.h>
#include <cstdint>

#define MDIM 8192
#define KDIM 8192
#define NDIM 8192

#define ROW_TILES 148
#define COL_TILES 8
#define NBLK (ROW_TILES * COL_TILES)   // 1184 = 148 SMs * 8 blocks/SM

// ---- scratch (device globals; no allocation allowed) ----
__device__ float g_partial[ROW_TILES * KDIM]; // 4.6 MiB
__device__ float g_wcs[KDIM];                 // 32 KiB

// ============================================================
// Kernel 1: partial column sums of W (proven loop, ~41.5us).
// Triggers programmatic launch of the reduce at block end.
// ============================================================
__global__ __launch_bounds__(256, 8) void colsum_partial(const float* __restrict__ w) {
    const int bid  = blockIdx.x;
    const int col4 = (bid & (COL_TILES - 1)) * 256 + threadIdx.x;
    const int rt   = bid >> 3;

    const float4* wp = reinterpret_cast<const float4*>(w) + col4;

    float4 acc = make_float4(0.f, 0.f, 0.f, 0.f);
    #pragma unroll 4
    for (int r = rt; r < NDIM; r += ROW_TILES) {
        float4 v = __ldcs(wp + (size_t)r * (KDIM / 4));
        acc.x += v.x; acc.y += v.y; acc.z += v.z; acc.w += v.w;
    }
    reinterpret_cast<float4*>(g_partial)[(size_t)rt * (KDIM / 4) + col4] = acc;

    cudaTriggerProgrammaticLaunchCompletion();
}

// ============================================================
// Kernel 2: fold 148 partials -> g_wcs (R8-proven scalar
// full-unroll shape; latency-bound, 32 blocks). PDL: triggers
// immediately so rowdot launches and prefetches x while this
// (and colsum's tail) still runs; griddepsync guards partials.
// ============================================================
__global__ __launch_bounds__(256) void colsum_reduce() {
    cudaTriggerProgrammaticLaunchCompletion();
    cudaGridDependencySynchronize();   // wait: colsum partials visible

    const int k = blockIdx.x * 256 + threadIdx.x;
    const float* p = g_partial + k;

    float s0 = 0.f, s1 = 0.f, s2 = 0.f, s3 = 0.f;
    #pragma unroll
    for (int rt = 0; rt < ROW_TILES; rt += 4) {
        s0 += p[(size_t)(rt + 0) * KDIM];
        s1 += p[(size_t)(rt + 1) * KDIM];
        s2 += p[(size_t)(rt + 2) * KDIM];
        s3 += p[(size_t)(rt + 3) * KDIM];
    }
    g_wcs[k] = (s0 + s1) + (s2 + s3);
}

// ============================================================
// Kernel 3: y[m] = 0.75 * dot(x[m,:], wcs). PDL-overlapped:
// the thread's ENTIRE x slice (8 independent LDG.128,
// wcs-independent) is prefetched BEFORE griddepsync, hiding
// the reduce kernel + launch gaps behind x streaming.
// ============================================================
__global__ __launch_bounds__(256) void rowdot(const float* __restrict__ x,
                                              float* __restrict__ y) {
    const int row = blockIdx.x;
    const int tid = threadIdx.x;
    const float4* xp = reinterpret_cast<const float4*>(x) + (size_t)row * (KDIM / 4);

    // prefetch x slice (independent of wcs)
    float4 a[8];
    #pragma unroll
    for (int j = 0; j < 8; ++j)
        a[j] = __ldcs(xp + tid + 256 * j);

    cudaGridDependencySynchronize();   // wait: g_wcs ready

    const float4* wp = reinterpret_cast<const float4*>(g_wcs);
    float s = 0.f;
    #pragma unroll
    for (int j = 0; j < 8; ++j) {
        float4 b = wp[tid + 256 * j];
        s += a[j].x * b.x + a[j].y * b.y + a[j].z * b.z + a[j].w * b.w;
    }

    #pragma unroll
    for (int off = 16; off > 0; off >>= 1)
        s += __shfl_xor_sync(0xFFFFFFFFu, s, off);

    __shared__ float red[8];
    if ((tid & 31) == 0) red[tid >> 5] = s;
    __syncthreads();
    if (tid < 8) {
        float t = red[tid];
        #pragma unroll
        for (int off = 4; off > 0; off >>= 1)
            t += __shfl_xor_sync(0xFFu, t, off);
        if (tid == 0) y[row] = 0.75f * t;
    }
}

extern "C" void kernel_launch(void* const* d_in, const int* in_sizes, int n_in,
                              void* d_out, int out_size) {
    const float* x = (const float*)d_in[0];  // [M, K]
    const float* w = (const float*)d_in[1];  // [N, K]
    float* y = (float*)d_out;                // [M, 1]

    // k1: normal launch
    colsum_partial<<<NBLK, 256>>>(w);

    // k2, k3: programmatic dependent launches (overlap with predecessor)
    cudaLaunchAttribute pdl;
    pdl.id = cudaLaunchAttributeProgrammaticStreamSerialization;
    pdl.val.programmaticStreamSerializationAllowed = 1;

    {
        cudaLaunchConfig_t cfg = {};
        cfg.gridDim = dim3(KDIM / 256);
        cfg.blockDim = dim3(256);
        cfg.attrs = &pdl;
        cfg.numAttrs = 1;
        cudaLaunchKernelEx(&cfg, colsum_reduce);
    }
    {
        cudaLaunchConfig_t cfg = {};
        cfg.gridDim = dim3(MDIM);
        cfg.blockDim = dim3(256);
        cfg.attrs = &pdl;
        cfg.numAttrs = 1;
        cudaLaunchKernelEx(&cfg, rowdot, x, y);
    }
}